// round 5
// baseline (speedup 1.0000x reference)
#include <cuda_runtime.h>
#include <stdint.h>

constexpr int THREADS = 128;
constexpr float HSTEP  = 0.05f;     // 0.5 * dt_eff
constexpr float DT_EFF = 0.1f;
constexpr float CMU_H  = 0.00125f;  // 0.5 * h * FRICTION_SCALE
constexpr float TWO_PI     = 6.2831853071795864769f;
constexpr float INV_TWO_PI = 0.15915494309189533577f;

// ---------------- helpers ----------------
__device__ __forceinline__ uint32_t bf2(float lo, float hi){
    uint32_t r;
    asm("cvt.rn.bf16x2.f32 %0, %1, %2;" : "=r"(r) : "f"(hi), "f"(lo));
    return r;
}
__device__ __forceinline__ void split2(float x0, float x1, uint32_t& hi, uint32_t& lo){
    hi = bf2(x0, x1);
    float h0 = __uint_as_float(hi << 16);
    float h1 = __uint_as_float(hi & 0xFFFF0000u);
    lo = bf2(x0 - h0, x1 - h1);
}
__device__ __forceinline__ float tanha(float x){
    float y; asm("tanh.approx.f32 %0, %1;" : "=f"(y) : "f"(x)); return y;
}
__device__ __forceinline__ float rdenf(float gate){
    float z = CMU_H * (1.0f + tanha(0.5f * gate));
    return fmaf(z, z, 1.0f) - z;
}
__device__ __forceinline__ void mma(float* c, uint32_t a0, uint32_t a1, uint32_t a2, uint32_t a3,
                                    uint32_t b0, uint32_t b1){
    asm("mma.sync.aligned.m16n8k16.row.col.f32.bf16.bf16.f32 "
        "{%0,%1,%2,%3}, {%4,%5,%6,%7}, {%8,%9}, {%0,%1,%2,%3};"
        : "+f"(c[0]), "+f"(c[1]), "+f"(c[2]), "+f"(c[3])
        : "r"(a0), "r"(a1), "r"(a2), "r"(a3), "r"(b0), "r"(b1));
}

// =====================================================================
// CTA = 128 thr = 4 warps. q = wid&1 selects a 16-row block, hh = wid>>1
// selects a 32-column half. Thread (g=lane>>4? no: g=lane>>2, m=lane&3)
// owns rows {g, g+8} and cols 32*hh + 8t + 2m + e (t=0..3,e=0..1):
// state idx = rr*8 + 2t + e  (16 elems per array).
// Warp pair {wid, wid^2} shares a row block; partials of K-split GEMMs
// are reduced through small padded SMEM buffers (1 barrier each).
// =====================================================================
__global__ void __launch_bounds__(THREADS, 3)
leapfrog_split_kernel(const float* __restrict__ x_in, const float* __restrict__ v_in,
                      const float* __restrict__ f_in, const float* __restrict__ U_in,
                      const float* __restrict__ W_in, const float* __restrict__ Wf_in,
                      const float* __restrict__ bf_in, const int* __restrict__ steps_ptr,
                      float* __restrict__ out, int Btot)
{
    __shared__ uint4 sWf[8 * 32 * 5];   // gate B-frags [ktg][lane][4 uint4 + pad]
    __shared__ uint4 sUl[32 * 5];       // U lo-frags  [lane][ktg 0..3 + pad]
    __shared__ uint4 sWl[32 * 5];       // W lo-frags  [lane][j 0..3 + pad]
    __shared__ float sBias[64];
    __shared__ float sExA[128 * 12];    // a-partial exchange (8 used, stride 12)
    __shared__ float sExB[128 * 28];    // fused exchange (24 used, stride 28)

    const int tid = threadIdx.x, wid = tid >> 5, lane = tid & 31;
    const int g = lane >> 2, m = lane & 3;
    const int q  = wid & 1;        // row-block
    const int hh = wid >> 1;       // column half
    const int r0 = blockIdx.x * 32 + q * 16 + g;
    const int cbase = 32 * hh + 2 * m;
    const int self    = (wid * 32 + lane);
    const int partner = ((wid ^ 2) * 32 + lane);

    // ---- gate B-frag table: Wf [64][128] -> B[n][k], all 8 k-tiles ----
    #pragma unroll
    for (int t = 0; t < 2; t++) {
        int kt = wid + 4 * t;
        #pragma unroll
        for (int j = 0; j < 4; j++) {
            const float* w0 = Wf_in + (8 * (2 * j)     + g) * 128 + 16 * kt;
            const float* w1 = Wf_in + (8 * (2 * j + 1) + g) * 128 + 16 * kt;
            uint4 qq;
            qq.x = bf2(w0[2 * m],     w0[2 * m + 1]);
            qq.y = bf2(w0[8 + 2 * m], w0[9 + 2 * m]);
            qq.z = bf2(w1[2 * m],     w1[2 * m + 1]);
            qq.w = bf2(w1[8 + 2 * m], w1[9 + 2 * m]);
            sWf[(kt * 32 + lane) * 5 + j] = qq;
        }
    }

    // ---- U frags (this warp's K-half): hi in regs, lo in smem ----
    uint32_t Uh[2][2][2];   // [ktl][nt][pair]
    {
        #pragma unroll
        for (int ktl = 0; ktl < 2; ktl++) {
            int ktg = 2 * hh + ktl;
            uint32_t lo[2][2];
            #pragma unroll
            for (int nt = 0; nt < 2; nt++) {
                const float* up = U_in + (8 * nt + g) * 64 + 16 * ktg;
                split2(up[2 * m],     up[2 * m + 1], Uh[ktl][nt][0], lo[nt][0]);
                split2(up[8 + 2 * m], up[9 + 2 * m], Uh[ktl][nt][1], lo[nt][1]);
            }
            if (q == 0)
                sUl[lane * 5 + ktg] = make_uint4(lo[0][0], lo[0][1], lo[1][0], lo[1][1]);
        }
    }

    // ---- W frags (this warp's N-half): hi in regs, lo in smem ----
    uint32_t Wh[4][2];      // [local n-tile j][pair]
    {
        uint32_t wlo[4][2];
        #pragma unroll
        for (int j = 0; j < 4; j++) {
            int n = 8 * (4 * hh + j) + g;
            split2(W_in[(2 * m) * 64 + n],     W_in[(2 * m + 1) * 64 + n], Wh[j][0], wlo[j][0]);
            split2(W_in[(2 * m + 8) * 64 + n], W_in[(2 * m + 9) * 64 + n], Wh[j][1], wlo[j][1]);
        }
        if (q == 0) {
            #pragma unroll
            for (int jj = 0; jj < 2; jj++)
                sWl[lane * 5 + 2 * hh + jj] =
                    make_uint4(wlo[2 * jj][0], wlo[2 * jj][1], wlo[2 * jj + 1][0], wlo[2 * jj + 1][1]);
        }
    }
    if (tid < 64) sBias[tid] = bf_in[tid];

    // ---- state into registers (16 per array) ----
    float xr[16], vr[16], fr[16], rden[16];
    #pragma unroll
    for (int rr = 0; rr < 2; rr++) {
        const size_t base = (size_t)(r0 + 8 * rr) * 64 + cbase;
        #pragma unroll
        for (int t = 0; t < 4; t++) {
            float2 tt;
            tt = *(const float2*)(x_in + base + 8 * t); xr[rr * 8 + 2 * t] = tt.x; xr[rr * 8 + 2 * t + 1] = tt.y;
            tt = *(const float2*)(v_in + base + 8 * t); vr[rr * 8 + 2 * t] = tt.x; vr[rr * 8 + 2 * t + 1] = tt.y;
            tt = *(const float2*)(f_in + base + 8 * t); fr[rr * 8 + 2 * t] = tt.x; fr[rr * 8 + 2 * t + 1] = tt.y;
        }
    }
    __syncthreads();

    float aC[2][4];     // reduced a (v.U^T), full R=16
    float gamC[4][4];   // gamma for this warp's 4 n-tiles

    // ---- one g1 k-block (this warp's K-half tile ktl) ----
    auto g1_block = [&](int ktl, float aH[2][4], float aL[2][4]){
        uint32_t ah0, ah1, ah2, ah3, al0, al1, al2, al3;
        split2(vr[4 * ktl],     vr[4 * ktl + 1], ah0, al0);
        split2(vr[8 + 4 * ktl], vr[9 + 4 * ktl], ah1, al1);
        split2(vr[4 * ktl + 2], vr[4 * ktl + 3], ah2, al2);
        split2(vr[10 + 4 * ktl], vr[11 + 4 * ktl], ah3, al3);
        uint4 ql = sUl[lane * 5 + 2 * hh + ktl];
        mma(aH[0], ah0, ah1, ah2, ah3, Uh[ktl][0][0], Uh[ktl][0][1]);
        mma(aH[1], ah0, ah1, ah2, ah3, Uh[ktl][1][0], Uh[ktl][1][1]);
        mma(aL[0], ah0, ah1, ah2, ah3, ql.x, ql.y);
        mma(aL[1], ah0, ah1, ah2, ah3, ql.z, ql.w);
        mma(aL[0], al0, al1, al2, al3, Uh[ktl][0][0], Uh[ktl][0][1]);
        mma(aL[1], al0, al1, al2, al3, Uh[ktl][1][0], Uh[ktl][1][1]);
    };

    // ---- standalone g1 partial + exchange through sExA ----
    auto g1_reduce = [&](){
        float aH[2][4], aL[2][4];
        #pragma unroll
        for (int nt = 0; nt < 2; nt++)
            #pragma unroll
            for (int k = 0; k < 4; k++) { aH[nt][k] = 0.f; aL[nt][k] = 0.f; }
        g1_block(0, aH, aL);
        g1_block(1, aH, aL);
        #pragma unroll
        for (int nt = 0; nt < 2; nt++) {
            float4 p = make_float4(aH[nt][0] + aL[nt][0], aH[nt][1] + aL[nt][1],
                                   aH[nt][2] + aL[nt][2], aH[nt][3] + aL[nt][3]);
            *(float4*)&sExA[self * 12 + 4 * nt] = p;
            aC[nt][0] = p.x; aC[nt][1] = p.y; aC[nt][2] = p.z; aC[nt][3] = p.w;
        }
        __syncthreads();
        #pragma unroll
        for (int nt = 0; nt < 2; nt++) {
            float4 p = *(const float4*)&sExA[partner * 12 + 4 * nt];
            aC[nt][0] += p.x; aC[nt][1] += p.y; aC[nt][2] += p.z; aC[nt][3] += p.w;
        }
    };

    // ---- fused: gate partial (+ optional g1 partial) + exchange via sExB ----
    auto fused_gate = [&](bool with_g1){
        float gc[8][4];
        #pragma unroll
        for (int nt = 0; nt < 8; nt++)
            #pragma unroll
            for (int k = 0; k < 4; k++) gc[nt][k] = 0.0f;
        float aH[2][4], aL[2][4];
        if (with_g1) {
            #pragma unroll
            for (int nt = 0; nt < 2; nt++)
                #pragma unroll
                for (int k = 0; k < 4; k++) { aH[nt][k] = 0.f; aL[nt][k] = 0.f; }
        }
        uint32_t cs[2][4];
        #pragma unroll
        for (int ktl = 0; ktl < 2; ktl++) {
            float s0, c0, s1, c1;
            uint32_t a0, a1, a2, a3;
            __sincosf(xr[4 * ktl],      &s0, &c0);
            __sincosf(xr[4 * ktl + 1],  &s1, &c1);
            a0 = bf2(s0, s1); cs[ktl][0] = bf2(c0, c1);
            __sincosf(xr[8 + 4 * ktl],  &s0, &c0);
            __sincosf(xr[9 + 4 * ktl],  &s1, &c1);
            a1 = bf2(s0, s1); cs[ktl][1] = bf2(c0, c1);
            __sincosf(xr[4 * ktl + 2],  &s0, &c0);
            __sincosf(xr[4 * ktl + 3],  &s1, &c1);
            a2 = bf2(s0, s1); cs[ktl][2] = bf2(c0, c1);
            __sincosf(xr[10 + 4 * ktl], &s0, &c0);
            __sincosf(xr[11 + 4 * ktl], &s1, &c1);
            a3 = bf2(s0, s1); cs[ktl][3] = bf2(c0, c1);
            int ktg = 2 * hh + ktl;   // sin k-tile
            #pragma unroll
            for (int j = 0; j < 4; j++) {
                uint4 qq = sWf[(ktg * 32 + lane) * 5 + j];
                mma(gc[2 * j],     a0, a1, a2, a3, qq.x, qq.y);
                mma(gc[2 * j + 1], a0, a1, a2, a3, qq.z, qq.w);
            }
            if (with_g1) g1_block(ktl, aH, aL);
        }
        #pragma unroll
        for (int ktl = 0; ktl < 2; ktl++) {
            int ktg = 4 + 2 * hh + ktl;   // cos k-tile
            #pragma unroll
            for (int j = 0; j < 4; j++) {
                uint4 qq = sWf[(ktg * 32 + lane) * 5 + j];
                mma(gc[2 * j],     cs[ktl][0], cs[ktl][1], cs[ktl][2], cs[ktl][3], qq.x, qq.y);
                mma(gc[2 * j + 1], cs[ktl][0], cs[ktl][1], cs[ktl][2], cs[ktl][3], qq.z, qq.w);
            }
        }
        // exchange: a-partial [0..7] + other-half gate partial [8..23]
        if (with_g1) {
            #pragma unroll
            for (int nt = 0; nt < 2; nt++) {
                float4 p = make_float4(aH[nt][0] + aL[nt][0], aH[nt][1] + aL[nt][1],
                                       aH[nt][2] + aL[nt][2], aH[nt][3] + aL[nt][3]);
                *(float4*)&sExB[self * 28 + 4 * nt] = p;
                aC[nt][0] = p.x; aC[nt][1] = p.y; aC[nt][2] = p.z; aC[nt][3] = p.w;
            }
        }
        const int oh = 1 - hh;
        #pragma unroll
        for (int j = 0; j < 4; j++)
            *(float4*)&sExB[self * 28 + 8 + 4 * j] = *(const float4*)gc[4 * oh + j];
        __syncthreads();
        if (with_g1) {
            #pragma unroll
            for (int nt = 0; nt < 2; nt++) {
                float4 p = *(const float4*)&sExB[partner * 28 + 4 * nt];
                aC[nt][0] += p.x; aC[nt][1] += p.y; aC[nt][2] += p.z; aC[nt][3] += p.w;
            }
        }
        #pragma unroll
        for (int j = 0; j < 4; j++) {
            float4 p = *(const float4*)&sExB[partner * 28 + 8 + 4 * j];
            float g0 = gc[4 * hh + j][0] + p.x;
            float g1v = gc[4 * hh + j][1] + p.y;
            float g2v = gc[4 * hh + j][2] + p.z;
            float g3 = gc[4 * hh + j][3] + p.w;
            float2 bb = *(const float2*)(sBias + 32 * hh + 8 * j + 2 * m);
            rden[2 * j]     = rdenf(g0 + bb.x);
            rden[2 * j + 1] = rdenf(g1v + bb.y);
            rden[8 + 2 * j] = rdenf(g2v + bb.x);
            rden[9 + 2 * j] = rdenf(g3 + bb.y);
        }
    };

    // ---- g2: gamma = (a*a) . W for this warp's 4 n-tiles ----
    auto g2 = [&](){
        uint32_t h0, h1, h2, h3, l0, l1, l2, l3;
        split2(aC[0][0] * aC[0][0], aC[0][1] * aC[0][1], h0, l0);
        split2(aC[0][2] * aC[0][2], aC[0][3] * aC[0][3], h1, l1);
        split2(aC[1][0] * aC[1][0], aC[1][1] * aC[1][1], h2, l2);
        split2(aC[1][2] * aC[1][2], aC[1][3] * aC[1][3], h3, l3);
        #pragma unroll
        for (int jj = 0; jj < 2; jj++) {
            uint4 ql = sWl[lane * 5 + 2 * hh + jj];
            uint32_t Wlf[2][2] = {{ql.x, ql.y}, {ql.z, ql.w}};
            #pragma unroll
            for (int u = 0; u < 2; u++) {
                int j = 2 * jj + u;
                #pragma unroll
                for (int k = 0; k < 4; k++) gamC[j][k] = 0.0f;
                mma(gamC[j], h0, h1, h2, h3, Wh[j][0], Wh[j][1]);
                mma(gamC[j], h0, h1, h2, h3, Wlf[u][0], Wlf[u][1]);
                mma(gamC[j], l0, l1, l2, l3, Wh[j][0], Wh[j][1]);
            }
        }
    };

    // ---- velocity (and position) update ----
    auto halfup = [&](bool first){
        #pragma unroll
        for (int j = 0; j < 4; j++) {
            #pragma unroll
            for (int k = 0; k < 4; k++) {
                int i = (k >> 1) * 8 + 2 * j + (k & 1);
                float vn = (vr[i] + HSTEP * (fr[i] - gamC[j][k])) * rden[i];
                vr[i] = vn;
                if (first) xr[i] = fmaf(DT_EFF, vn, xr[i]);
            }
        }
    };

    // ---- initial friction at x0 ----
    fused_gate(false);

    // ---- main loop ----
    const int steps = steps_ptr[0];
    for (int s = 0; s < steps; s++) {
        g1_reduce();               // a(v), reduced across K-halves
        g2(); halfup(true);        // v_half, x update (rden = mu at old x)
        fused_gate(true);          // mu(x_new) + a(v_half), reduced
        g2(); halfup(false);       // final v
    }

    // ---- output: wrap x, write x then v ----
    #pragma unroll
    for (int rr = 0; rr < 2; rr++) {
        const size_t base = (size_t)(r0 + 8 * rr) * 64 + cbase;
        #pragma unroll
        for (int t = 0; t < 4; t++) {
            float X0 = xr[rr * 8 + 2 * t], X1 = xr[rr * 8 + 2 * t + 1];
            float2 qx;
            qx.x = fmaf(-TWO_PI, rintf(X0 * INV_TWO_PI), X0);
            qx.y = fmaf(-TWO_PI, rintf(X1 * INV_TWO_PI), X1);
            *(float2*)(out + base + 8 * t) = qx;
            float2 qv = make_float2(vr[rr * 8 + 2 * t], vr[rr * 8 + 2 * t + 1]);
            *(float2*)(out + (size_t)Btot * 64 + base + 8 * t) = qv;
        }
    }
}

extern "C" void kernel_launch(void* const* d_in, const int* in_sizes, int n_in,
                              void* d_out, int out_size)
{
    const float* x  = (const float*)d_in[0];
    const float* v  = (const float*)d_in[1];
    const float* f  = (const float*)d_in[2];
    const float* U  = (const float*)d_in[3];
    const float* W  = (const float*)d_in[4];
    const float* Wf = (const float*)d_in[5];
    const float* bf = (const float*)d_in[6];
    const int* steps = (const int*)d_in[7];

    float* out = (float*)d_out;
    const int Btot = in_sizes[0] / 64;     // 262144
    const int blocks = Btot / 32;          // 8192 (32 rows per CTA, 4 warps)

    leapfrog_split_kernel<<<blocks, THREADS>>>(x, v, f, U, W, Wf, bf, steps, out, Btot);
}